// round 16
// baseline (speedup 1.0000x reference)
#include <cuda_runtime.h>
#include <math.h>

#define MAXN   16384
#define HDIM   128
#define TM     64
#define THRS   5e-5f

// ---------------- device state ----------------
__device__ float g_start[MAXN], g_end[MAXN];
__device__ float g_next_s[MAXN], g_next_e[MAXN];
__device__ float g_curr_s[MAXN], g_curr_e[MAXN];
__device__ unsigned char g_uf_s[MAXN], g_uf_e[MAXN];
__device__ unsigned char g_workf[MAXN], g_secf[MAXN], g_convf[MAXN];
__device__ float g_zlow[MAXN], g_zhigh[MAXN], g_slow[MAXN], g_shigh[MAXN];
__device__ float g_zpred[MAXN], g_cand[MAXN];
__device__ int g_cnt[64];
__device__ int g_la[MAXN], g_lb[MAXN], g_lc[MAXN], g_ld[MAXN], g_lw[MAXN], g_ls[MAXN];
__device__ unsigned int g_barc = 0u, g_gen = 0u;

// jax.nn.softplus(x) = max(x,0) + log1p(exp(-|x|))  [libdevice expf/log1pf]
__device__ __forceinline__ float softplus_x(float x) {
    return __fadd_rn(fmaxf(x, 0.0f), log1pf(expf(-fabsf(x))));
}
// jnp.linspace(0,1,64)[i]
__device__ __forceinline__ float lint(int i) {
    return (i == 63) ? 1.0f : __fdiv_rn((float)i, 63.0f);
}
// pts_int = start + t*(end-start), uncontracted rn
__device__ __forceinline__ float ptsint(float s, float e, float t) {
    return __fadd_rn(s, __fmul_rn(t, __fsub_rn(e, s)));
}

// ---- packed fp32 FFMA2 (lane-wise IEEE rn — bit-identical to 2 scalar chains)
__device__ __forceinline__ unsigned long long pack2same(float v) {
    unsigned long long r;
    asm("mov.b64 %0, {%1, %2};" : "=l"(r) : "f"(v), "f"(v));
    return r;
}
__device__ __forceinline__ unsigned long long fma2(unsigned long long a,
                                                   unsigned long long b,
                                                   unsigned long long c) {
    unsigned long long d;
    asm("fma.rn.f32x2 %0, %1, %2, %3;" : "=l"(d) : "l"(a), "l"(b), "l"(c));
    return d;
}
__device__ __forceinline__ void unpack2(unsigned long long v, float& lo, float& hi) {
    asm("mov.b64 {%0, %1}, %2;" : "=f"(lo), "=f"(hi) : "l"(v));
}

// ---------------- software grid barrier ----------------
// Safe: grid sized to guaranteed co-residency (SMs x occupancy).
__device__ __forceinline__ void gridbar(int nb) {
    __syncthreads();
    if (threadIdx.x == 0) {
        unsigned int gen = atomicAdd(&g_gen, 0u);
        __threadfence();                                   // release prior writes
        if (atomicAdd(&g_barc, 1u) == (unsigned int)nb - 1u) {
            atomicExch(&g_barc, 0u);
            __threadfence();
            atomicAdd(&g_gen, 1u);                         // release
        } else {
            while (atomicAdd(&g_gen, 0u) == gen) { }       // spin (L2 atomics)
        }
        __threadfence();                                   // acquire
    }
    __syncthreads();
}

// ---------------- shared layout (floats), TM=64 ----------------
// Union: HsT (128x64, pitch 64 = 8192) during GEMM; H3 (64 rows, pitch 129 = 8256) after.
#define SOFF_HH   0
#define SOFF_PS   8256
#define SOFF_W1   8512
#define SOFF_B1   8896
#define SOFF_B2   9024
#define SOFF_W3   9152
#define SOFF_B3   9280
#define SOFF_OIX  9284
#define SOFF_SV   9348
#define EVAL_SMEM ((9348 + 72) * 4)   // ~36.8 KB -> 4 blocks/SM

// ---------------- eval phase (persistent tile loop) ----------------
// Per-point math bit-identical to the passing r7-r15 kernels.
// MODE 0: li -> ray=list[li], t=tvals[ray]. MODE 1: dense march, 1 ray/tile.
// FUSE: 0=plain write, 1=linestep epilogue, 2=secant-update epilogue.
// TWO: number of sides processed.
template <int MODE, int FUSE, int TWO>
__device__ void eval_phase(
    int cidxA, int cidxB, int xA, int xB, int nb,
    const float* __restrict__ rayo, const float* __restrict__ rayd,
    const float* __restrict__ W2,
    const int* __restrict__ listA, const int* __restrict__ listB,
    const float* __restrict__ tvalsA, const float* __restrict__ tvalsB,
    float* __restrict__ outA, float* __restrict__ outB,
    const int* __restrict__ obj)
{
    extern __shared__ float sbuf[];
    float* HsT = sbuf + SOFF_HH;
    float* H3  = sbuf + SOFF_HH;
    float* Ps  = sbuf + SOFF_PS;
    float* w1s = sbuf + SOFF_W1;
    float* b1s = sbuf + SOFF_B1;
    float* b2s = sbuf + SOFF_B2;
    float* w3s = sbuf + SOFF_W3;
    float* b3s = sbuf + SOFF_B3;
    float* svs = sbuf + SOFF_SV;
    int*   oix = (int*)(sbuf + SOFF_OIX);

    const int tid = threadIdx.x;
    const int cntA = g_cnt[cidxA];
    const int tilesA = (MODE == 1) ? cntA : (cntA + TM - 1) / TM;
    int cntB = 0, tilesB = 0;
    if (TWO == 2) { cntB = g_cnt[cidxB]; tilesB = (cntB + TM - 1) / TM; }

    for (int t = blockIdx.x; t < tilesA + tilesB; t += nb) {
        const int side = (t >= tilesA) ? 1 : 0;
        const int lb   = side ? (t - tilesA) : t;
        const int rcnt = side ? cntB : cntA;
        const int pcnt = (MODE == 1) ? (rcnt << 6) : rcnt;
        const int*   list  = side ? listB  : listA;
        const float* tvals = side ? tvalsB : tvalsA;
        float*       outp  = side ? outB   : outA;

        if (tid < TM) {
            int li = lb * TM + tid;
            int oi = -1;
            float px = 0.f, py = 0.f, pz = 0.f;
            if (li < pcnt) {
                int ray; float tt;
                if (MODE == 0) {
                    ray = list[li];
                    tt = tvals[ray];
                    oi = ray;
                } else {
                    ray = list[li >> 6];
                    tt = ptsint(g_start[ray], g_end[ray], lint(li & 63));
                    oi = li;
                }
                px = __fadd_rn(rayo[ray * 3 + 0], __fmul_rn(tt, rayd[ray * 3 + 0]));
                py = __fadd_rn(rayo[ray * 3 + 1], __fmul_rn(tt, rayd[ray * 3 + 1]));
                pz = __fadd_rn(rayo[ray * 3 + 2], __fmul_rn(tt, rayd[ray * 3 + 2]));
            }
            Ps[tid * 4 + 0] = px; Ps[tid * 4 + 1] = py; Ps[tid * 4 + 2] = pz; Ps[tid * 4 + 3] = 0.f;
            oix[tid] = oi;
        }
        __syncthreads();

        // layer 1 (HsT pitch 64)
        for (int idx = tid; idx < HDIM * TM; idx += 256) {
            int k = idx >> 6, m = idx & 63;
            float v = __fmaf_rn(Ps[m * 4 + 0], w1s[k], 0.0f);
            v = __fmaf_rn(Ps[m * 4 + 1], w1s[HDIM + k], v);
            v = __fmaf_rn(Ps[m * 4 + 2], w1s[2 * HDIM + k], v);
            v = __fadd_rn(v, b1s[k]);
            HsT[k * TM + m] = softplus_x(v);
        }
        __syncthreads();

        // layer 2: packed f32x2 over j-pairs; ascending-k chains per element
        const int tx = tid & 15, ty = tid >> 4;
        unsigned long long acc2[4][4];
        #pragma unroll
        for (int i = 0; i < 4; i++)
            #pragma unroll
            for (int jp = 0; jp < 4; jp++) acc2[i][jp] = 0ull;
        const float* hp = HsT + ty * 4;
        const float* wp = W2 + tx * 8;
        #pragma unroll 4
        for (int k = 0; k < HDIM; k++) {
            float4 a0 = *(const float4*)(hp + k * TM);
            ulonglong2 w0 = *(const ulonglong2*)(wp + k * HDIM);
            ulonglong2 w1p = *(const ulonglong2*)(wp + k * HDIM + 4);
            unsigned long long bv2[4] = {w0.x, w0.y, w1p.x, w1p.y};
            float av[4] = {a0.x, a0.y, a0.z, a0.w};
            #pragma unroll
            for (int i = 0; i < 4; i++) {
                unsigned long long a2 = pack2same(av[i]);
                #pragma unroll
                for (int jp = 0; jp < 4; jp++)
                    acc2[i][jp] = fma2(a2, bv2[jp], acc2[i][jp]);
            }
        }
        __syncthreads();   // HsT reads done -> overwrite with H3

        #pragma unroll
        for (int i = 0; i < 4; i++) {
            int m = ty * 4 + i;
            #pragma unroll
            for (int jp = 0; jp < 4; jp++) {
                float lo, hi;
                unpack2(acc2[i][jp], lo, hi);
                int n = tx * 8 + jp * 2;
                H3[m * 129 + n]     = softplus_x(__fadd_rn(lo, b2s[n]));
                H3[m * 129 + n + 1] = softplus_x(__fadd_rn(hi, b2s[n + 1]));
            }
        }
        __syncthreads();

        // layer 3: gemv2T-8 order + fused epilogues
        {
            int grp = tid >> 3;
            int l8  = tid & 7;
            #pragma unroll
            for (int rep = 0; rep < 2; rep++) {
                int m = rep * 32 + grp;
                const float* hrow = H3 + m * 129;
                float p = 0.0f;
                #pragma unroll
                for (int i = 0; i < 16; i++)
                    p = __fmaf_rn(hrow[l8 + 8 * i], w3s[l8 + 8 * i], p);
                p = __fadd_rn(p, __shfl_down_sync(0xffffffffu, p, 4, 8));
                p = __fadd_rn(p, __shfl_down_sync(0xffffffffu, p, 2, 8));
                p = __fadd_rn(p, __shfl_down_sync(0xffffffffu, p, 1, 8));
                if (l8 == 0) {
                    float corr = __fadd_rn(p, b3s[0]);
                    float px = Ps[m * 4 + 0], py = Ps[m * 4 + 1], pz = Ps[m * 4 + 2];
                    float s2 = __fadd_rn(__fadd_rn(__fmul_rn(px, px), __fmul_rn(py, py)), __fmul_rn(pz, pz));
                    float nr = __fsqrt_rn(s2);
                    float sv = __fadd_rn(__fsub_rn(nr, 1.0f), __fmul_rn(0.1f, corr));
                    int oi = oix[m];
                    if (MODE == 1) {
                        svs[m] = sv;
                    } else if (oi >= 0) {
                        int ray = oi;
                        if (FUSE == 0) {
                            outp[ray] = sv;
                        } else if (FUSE == 1) {
                            outp[ray] = sv;
                            if (sv < 0.f) {
                                if (side == 0) {
                                    g_start[ray] = __fsub_rn(g_start[ray], __fmul_rn(0.5f, g_curr_s[ray]));
                                    int pp = atomicAdd(&g_cnt[xA], 1); g_lc[pp] = ray;
                                } else {
                                    g_end[ray] = __fadd_rn(g_end[ray], __fmul_rn(0.5f, g_curr_e[ray]));
                                    int pp = atomicAdd(&g_cnt[xB], 1); g_ld[pp] = ray;
                                }
                            }
                        } else {
                            float smv = sv;
                            float zl = g_zlow[ray], zh = g_zhigh[ray], sl = g_slow[ray], sh = g_shigh[ray];
                            float zp = g_zpred[ray];
                            if (smv > 0.f) { zl = zp; sl = smv; }
                            if (smv < 0.f) { zh = zp; sh = smv; }
                            float num = __fmul_rn(-sl, __fsub_rn(zh, zl));
                            float den = __fadd_rn(__fsub_rn(sh, sl), 1e-10f);
                            zp = __fadd_rn(__fdiv_rn(num, den), zl);
                            g_zlow[ray] = zl; g_zhigh[ray] = zh; g_slow[ray] = sl; g_shigh[ray] = sh;
                            g_zpred[ray] = zp;
                        }
                    }
                }
            }
        }

        // MODE 1: tile = 1 ray; fused argmin reduce + secant init
        if (MODE == 1) {
            __syncthreads();
            int warp = tid >> 5, lane = tid & 31;
            if (warp == 0 && lb < rcnt) {
                int ray = list[lb];
                const float* sp = svs;
                float s0 = sp[lane];
                float s1 = sp[lane + 32];
                float sg0 = (s0 > 0.f ? 1.f : (s0 < 0.f ? -1.f : 0.f));
                float sg1 = (s1 > 0.f ? 1.f : (s1 < 0.f ? -1.f : 0.f));
                float t0 = sg0 * (float)(64 - lane);
                float t1 = sg1 * (float)(32 - lane);

                float bv; int bi;
                if (t1 < t0) { bv = t1; bi = lane + 32; } else { bv = t0; bi = lane; }
                float cv; int ci;
                if (s1 < s0) { cv = s1; ci = lane + 32; } else { cv = s0; ci = lane; }
                #pragma unroll
                for (int off = 16; off > 0; off >>= 1) {
                    float ov = __shfl_down_sync(0xffffffffu, bv, off);
                    int   oi2 = __shfl_down_sync(0xffffffffu, bi, off);
                    if (ov < bv || (ov == bv && oi2 < bi)) { bv = ov; bi = oi2; }
                    float pv = __shfl_down_sync(0xffffffffu, cv, off);
                    int   pi = __shfl_down_sync(0xffffffffu, ci, off);
                    if (pv < cv || (pv == cv && pi < ci)) { cv = pv; ci = pi; }
                }
                if (lane == 0) {
                    int idx = bi;
                    bool net = (bv < 0.f);
                    int out_idx = ci;
                    bool ob = (obj[ray] != 0);
                    bool p_out = !(ob && net);
                    int sel = p_out ? out_idx : idx;
                    float s = g_start[ray], e = g_end[ray];
                    g_cand[ray]  = ptsint(s, e, lint(sel));
                    g_convf[ray] = net ? 1 : 0;
                    if (net && ob) {
                        g_secf[ray] = 1;
                        int il = (idx + 63) & 63;
                        float zh = ptsint(s, e, lint(idx));
                        float zl = ptsint(s, e, lint(il));
                        float sh = sp[idx];
                        float sl = sp[il];
                        g_zlow[ray] = zl; g_zhigh[ray] = zh; g_slow[ray] = sl; g_shigh[ray] = sh;
                        float num = __fmul_rn(-sl, __fsub_rn(zh, zl));
                        float den = __fadd_rn(__fsub_rn(sh, sl), 1e-10f);
                        g_zpred[ray] = __fadd_rn(__fdiv_rn(num, den), zl);
                        int pp = atomicAdd(&g_cnt[xA], 1); g_ls[pp] = ray;
                    }
                }
            }
        }
        __syncthreads();   // end of tile (H3/svs reuse safety)
    }
}

// ---------------- persistent kernel: whole pipeline ----------------
__global__ void __launch_bounds__(256, 4) persist_kernel(
    int N, int nb,
    const float* __restrict__ rayo, const float* __restrict__ rayd,
    const float* __restrict__ fb,
    const float* __restrict__ W1, const float* __restrict__ b1,
    const float* __restrict__ W2, const float* __restrict__ b2,
    const float* __restrict__ W3, const float* __restrict__ b3,
    const int* __restrict__ obj, const int* __restrict__ mi,
    float* __restrict__ out)
{
    extern __shared__ float sbuf[];
    float* w1s = sbuf + SOFF_W1;
    float* b1s = sbuf + SOFF_B1;
    float* b2s = sbuf + SOFF_B2;
    float* w3s = sbuf + SOFF_W3;
    float* b3s = sbuf + SOFF_B3;

    const int tid = threadIdx.x;
    const int gt = blockIdx.x * 256 + tid;
    const int gs = nb * 256;

    // weights -> smem once for the whole run
    for (int i = tid; i < 3 * HDIM; i += 256) w1s[i] = W1[i];
    if (tid < HDIM) { b1s[tid] = b1[tid]; b2s[tid] = b2[tid]; w3s[tid] = W3[tid]; }
    if (tid == 0) b3s[0] = b3[0];
    __syncthreads();

    // ---- init phase ----
    for (int i = gt; i < N; i += gs) {
        g_start[i] = fb[2 * i];
        g_end[i]   = fb[2 * i + 1];
        unsigned char m = mi[i] ? 1 : 0;
        g_uf_s[i] = m; g_uf_e[i] = m;
        g_next_s[i] = 0.f; g_next_e[i] = 0.f;
        g_workf[i] = 0; g_secf[i] = 0; g_convf[i] = 0;
        if (m) { int p = atomicAdd(&g_cnt[0], 1); g_la[p] = i; }
    }
    gridbar(nb);

    // ---- initial next_s/next_e ----
    eval_phase<0, 0, 2>(0, 0, 0, 0, nb, rayo, rayd, W2, g_la, g_la,
                        g_start, g_end, g_next_s, g_next_e, obj);
    gridbar(nb);

    // ---- sphere tracing loop ----
    for (int it = 0; it < 10; it++) {
        int c1 = 1 + it * 4, c2 = 2 + it * 4, c3 = 3 + it * 4, c4 = 4 + it * 4;
        int apply_lt = (it > 0) ? 1 : 0;
        for (int i = gt; i < N; i += gs) {
            unsigned char us = g_uf_s[i], ue = g_uf_e[i];
            float s = g_start[i], e = g_end[i];
            if (apply_lt) { unsigned char lt = (s < e) ? 1 : 0; us &= lt; ue &= lt; }
            float cs = us ? g_next_s[i] : 0.f; if (cs <= THRS) cs = 0.f;
            float ce = ue ? g_next_e[i] : 0.f; if (ce <= THRS) ce = 0.f;
            us = (us && cs > THRS) ? 1 : 0;
            ue = (ue && ce > THRS) ? 1 : 0;
            if (us) s = __fadd_rn(s, cs);
            if (ue) e = __fsub_rn(e, ce);
            g_start[i] = s; g_end[i] = e;
            g_curr_s[i] = cs; g_curr_e[i] = ce;
            g_uf_s[i] = us; g_uf_e[i] = ue;
            if (!us) g_next_s[i] = 0.f;
            if (!ue) g_next_e[i] = 0.f;
            if (us) { int p = atomicAdd(&g_cnt[c1], 1); g_la[p] = i; }
            if (ue) { int p = atomicAdd(&g_cnt[c2], 1); g_lb[p] = i; }
        }
        gridbar(nb);
        eval_phase<0, 1, 2>(c1, c2, c3, c4, nb, rayo, rayd, W2, g_la, g_lb,
                            g_start, g_end, g_next_s, g_next_e, obj);
        gridbar(nb);
        eval_phase<0, 0, 2>(c3, c4, 0, 0, nb, rayo, rayd, W2, g_lc, g_ld,
                            g_start, g_end, g_next_s, g_next_e, obj);
        gridbar(nb);
    }

    // ---- work mask ----
    for (int i = gt; i < N; i += gs) {
        unsigned char us = g_uf_s[i];
        if (!(g_start[i] < g_end[i])) us = 0;
        unsigned char w = (us && (g_next_s[i] > THRS)) ? 1 : 0;
        g_workf[i] = w;
        if (w) { int p = atomicAdd(&g_cnt[48], 1); g_lw[p] = i; }
    }
    gridbar(nb);

    // ---- dense 64-step march + fused reduce + secant init ----
    eval_phase<1, 0, 1>(48, 48, 49, 49, nb, rayo, rayd, W2, g_lw, g_lw,
                        g_start, g_start, g_next_s, g_next_s, obj);
    gridbar(nb);

    // ---- secant iterations (fused update) ----
    for (int it = 0; it < 8; it++) {
        eval_phase<0, 2, 1>(49, 49, 0, 0, nb, rayo, rayd, W2, g_ls, g_ls,
                            g_zpred, g_zpred, g_next_s, g_next_s, obj);
        gridbar(nb);
    }

    // ---- assembly ----
    for (int i = gt; i < N; i += gs) {
        float px = 0.f, py = 0.f, pz = 0.f, dist = 0.f;
        if (g_secf[i]) {
            float t = g_zpred[i];
            px = __fadd_rn(rayo[i*3+0], __fmul_rn(t, rayd[i*3+0]));
            py = __fadd_rn(rayo[i*3+1], __fmul_rn(t, rayd[i*3+1]));
            pz = __fadd_rn(rayo[i*3+2], __fmul_rn(t, rayd[i*3+2]));
            dist = t;
        } else if (g_workf[i]) {
            float t = g_cand[i];
            px = __fadd_rn(rayo[i*3+0], __fmul_rn(t, rayd[i*3+0]));
            py = __fadd_rn(rayo[i*3+1], __fmul_rn(t, rayd[i*3+1]));
            pz = __fadd_rn(rayo[i*3+2], __fmul_rn(t, rayd[i*3+2]));
            dist = t;
        }
        out[i*5+0] = px; out[i*5+1] = py; out[i*5+2] = pz;
        out[i*5+3] = dist;
        out[i*5+4] = g_convf[i] ? 1.0f : 0.0f;
    }
}

// ---------------- counter reset ----------------
__global__ void reset_kernel() {
    if (threadIdx.x < 64) g_cnt[threadIdx.x] = 0;
}

// ---------------- host orchestration ----------------
extern "C" void kernel_launch(void* const* d_in, const int* in_sizes, int n_in,
                              void* d_out, int out_size)
{
    const float* rayo = (const float*)d_in[0];
    const float* rayd = (const float*)d_in[1];
    const float* fb   = (const float*)d_in[2];
    const float* W1   = (const float*)d_in[3];
    const float* b1   = (const float*)d_in[4];
    const float* W2   = (const float*)d_in[5];
    const float* b2   = (const float*)d_in[6];
    const float* W3   = (const float*)d_in[7];
    const float* b3   = (const float*)d_in[8];
    const int* obj    = (const int*)d_in[9];
    const int* mi     = (const int*)d_in[10];
    int N = in_sizes[0] / 3;
    float* out = (float*)d_out;

    cudaFuncSetAttribute(persist_kernel, cudaFuncAttributeMaxDynamicSharedMemorySize, EVAL_SMEM);

    int dev = 0, sms = 0, occ = 0;
    cudaGetDevice(&dev);
    cudaDeviceGetAttribute(&sms, cudaDevAttrMultiProcessorCount, dev);
    cudaOccupancyMaxActiveBlocksPerMultiprocessor(&occ, persist_kernel, 256, EVAL_SMEM);
    if (occ < 1) occ = 1;
    int nb = sms * occ;
    if (nb < 1) nb = 148;

    reset_kernel<<<1, 64>>>();
    persist_kernel<<<nb, 256, EVAL_SMEM>>>(N, nb, rayo, rayd, fb,
                                           W1, b1, W2, b2, W3, b3, obj, mi, out);
    (void)n_in; (void)out_size; (void)b2;
}

// round 17
// speedup vs baseline: 1.0996x; 1.0996x over previous
#include <cuda_runtime.h>
#include <math.h>

#define MAXN   16384
#define HDIM   128
#define TM     64
#define THRS   5e-5f

// ---------------- device state ----------------
__device__ float g_start[MAXN], g_end[MAXN];
__device__ float g_next_s[MAXN], g_next_e[MAXN];
__device__ float g_curr_s[MAXN], g_curr_e[MAXN];
__device__ unsigned char g_uf_s[MAXN], g_uf_e[MAXN];
__device__ unsigned char g_workf[MAXN], g_secf[MAXN], g_convf[MAXN];
__device__ float g_zlow[MAXN], g_zhigh[MAXN], g_slow[MAXN], g_shigh[MAXN];
__device__ float g_zpred[MAXN], g_cand[MAXN];
__device__ int g_cnt[64];
__device__ int g_la[MAXN], g_lb[MAXN], g_lc[MAXN], g_ld[MAXN], g_lw[MAXN], g_ls[MAXN];
__device__ unsigned int g_barc = 0u, g_gen = 0u;

// jax.nn.softplus(x) = max(x,0) + log1p(exp(-|x|))  [libdevice expf/log1pf]
__device__ __forceinline__ float softplus_x(float x) {
    return __fadd_rn(fmaxf(x, 0.0f), log1pf(expf(-fabsf(x))));
}
// jnp.linspace(0,1,64)[i]
__device__ __forceinline__ float lint(int i) {
    return (i == 63) ? 1.0f : __fdiv_rn((float)i, 63.0f);
}
// pts_int = start + t*(end-start), uncontracted rn
__device__ __forceinline__ float ptsint(float s, float e, float t) {
    return __fadd_rn(s, __fmul_rn(t, __fsub_rn(e, s)));
}

// ---- packed fp32 FFMA2 (lane-wise IEEE rn — bit-identical to 2 scalar chains)
__device__ __forceinline__ unsigned long long pack2same(float v) {
    unsigned long long r;
    asm("mov.b64 %0, {%1, %2};" : "=l"(r) : "f"(v), "f"(v));
    return r;
}
__device__ __forceinline__ unsigned long long fma2(unsigned long long a,
                                                   unsigned long long b,
                                                   unsigned long long c) {
    unsigned long long d;
    asm("fma.rn.f32x2 %0, %1, %2, %3;" : "=l"(d) : "l"(a), "l"(b), "l"(c));
    return d;
}
__device__ __forceinline__ void unpack2(unsigned long long v, float& lo, float& hi) {
    asm("mov.b64 {%0, %1}, %2;" : "=f"(lo), "=f"(hi) : "l"(v));
}

// ---------------- software grid barrier (low-contention) ----------------
// Arrivals: one atomic per block. Wait: plain volatile load + nanosleep backoff
// (no RMW in the spin -> LTS atomic unit stays free for arrivals).
__device__ __forceinline__ void gridbar(int nb) {
    __syncthreads();
    if (threadIdx.x == 0) {
        volatile unsigned int* genp = &g_gen;
        unsigned int gen = *genp;                          // read BEFORE arriving
        __threadfence();                                   // release prior writes
        if (atomicAdd(&g_barc, 1u) == (unsigned int)nb - 1u) {
            atomicExch(&g_barc, 0u);
            __threadfence();
            atomicAdd(&g_gen, 1u);                         // release
        } else {
            while (*genp == gen) { __nanosleep(64); }      // backoff spin
        }
        __threadfence();                                   // acquire
    }
    __syncthreads();
}

// ---------------- shared layout (floats), TM=64 ----------------
// Union: HsT (128x64, pitch 64 = 8192) during GEMM; H3 (64 rows, pitch 129 = 8256) after.
#define SOFF_HH   0
#define SOFF_PS   8256
#define SOFF_W1   8512
#define SOFF_B1   8896
#define SOFF_B2   9024
#define SOFF_W3   9152
#define SOFF_B3   9280
#define SOFF_OIX  9284
#define SOFF_SV   9348
#define EVAL_SMEM ((9348 + 72) * 4)   // ~36.8 KB -> 4 blocks/SM

// ---------------- eval phase (persistent tile loop) ----------------
// Per-point math bit-identical to the passing r7-r15 kernels.
// MODE 0: li -> ray=list[li], t=tvals[ray]. MODE 1: dense march, 1 ray/tile.
// FUSE: 0=plain write, 1=linestep epilogue, 2=secant-update epilogue.
// TWO: number of sides. ITERS: in-tile repeat count (secant: 8; per-ray
// independent, so no grid barrier needed between iterations).
template <int MODE, int FUSE, int TWO, int ITERS>
__device__ void eval_phase(
    int cidxA, int cidxB, int xA, int xB, int nb,
    const float* __restrict__ rayo, const float* __restrict__ rayd,
    const float* __restrict__ W2,
    const int* __restrict__ listA, const int* __restrict__ listB,
    const float* __restrict__ tvalsA, const float* __restrict__ tvalsB,
    float* __restrict__ outA, float* __restrict__ outB,
    const int* __restrict__ obj)
{
    extern __shared__ float sbuf[];
    float* HsT = sbuf + SOFF_HH;
    float* H3  = sbuf + SOFF_HH;
    float* Ps  = sbuf + SOFF_PS;
    float* w1s = sbuf + SOFF_W1;
    float* b1s = sbuf + SOFF_B1;
    float* b2s = sbuf + SOFF_B2;
    float* w3s = sbuf + SOFF_W3;
    float* b3s = sbuf + SOFF_B3;
    float* svs = sbuf + SOFF_SV;
    int*   oix = (int*)(sbuf + SOFF_OIX);

    const int tid = threadIdx.x;
    const int cntA = g_cnt[cidxA];
    const int tilesA = (MODE == 1) ? cntA : (cntA + TM - 1) / TM;
    int cntB = 0, tilesB = 0;
    if (TWO == 2) { cntB = g_cnt[cidxB]; tilesB = (cntB + TM - 1) / TM; }

    for (int t = blockIdx.x; t < tilesA + tilesB; t += nb) {
        const int side = (t >= tilesA) ? 1 : 0;
        const int lb   = side ? (t - tilesA) : t;
        const int rcnt = side ? cntB : cntA;
        const int pcnt = (MODE == 1) ? (rcnt << 6) : rcnt;
        const int*   list  = side ? listB  : listA;
        const float* tvals = side ? tvalsB : tvalsA;
        float*       outp  = side ? outB   : outA;

        for (int itn = 0; itn < ITERS; itn++) {
            if (tid < TM) {
                int li = lb * TM + tid;
                int oi = -1;
                float px = 0.f, py = 0.f, pz = 0.f;
                if (li < pcnt) {
                    int ray; float tt;
                    if (MODE == 0) {
                        ray = list[li];
                        tt = tvals[ray];
                        oi = ray;
                    } else {
                        ray = list[li >> 6];
                        tt = ptsint(g_start[ray], g_end[ray], lint(li & 63));
                        oi = li;
                    }
                    px = __fadd_rn(rayo[ray * 3 + 0], __fmul_rn(tt, rayd[ray * 3 + 0]));
                    py = __fadd_rn(rayo[ray * 3 + 1], __fmul_rn(tt, rayd[ray * 3 + 1]));
                    pz = __fadd_rn(rayo[ray * 3 + 2], __fmul_rn(tt, rayd[ray * 3 + 2]));
                }
                Ps[tid * 4 + 0] = px; Ps[tid * 4 + 1] = py; Ps[tid * 4 + 2] = pz; Ps[tid * 4 + 3] = 0.f;
                oix[tid] = oi;
            }
            __syncthreads();

            // layer 1 (HsT pitch 64)
            for (int idx = tid; idx < HDIM * TM; idx += 256) {
                int k = idx >> 6, m = idx & 63;
                float v = __fmaf_rn(Ps[m * 4 + 0], w1s[k], 0.0f);
                v = __fmaf_rn(Ps[m * 4 + 1], w1s[HDIM + k], v);
                v = __fmaf_rn(Ps[m * 4 + 2], w1s[2 * HDIM + k], v);
                v = __fadd_rn(v, b1s[k]);
                HsT[k * TM + m] = softplus_x(v);
            }
            __syncthreads();

            // layer 2: packed f32x2 over j-pairs; ascending-k chains per element
            const int tx = tid & 15, ty = tid >> 4;
            unsigned long long acc2[4][4];
            #pragma unroll
            for (int i = 0; i < 4; i++)
                #pragma unroll
                for (int jp = 0; jp < 4; jp++) acc2[i][jp] = 0ull;
            const float* hp = HsT + ty * 4;
            const float* wp = W2 + tx * 8;
            #pragma unroll 4
            for (int k = 0; k < HDIM; k++) {
                float4 a0 = *(const float4*)(hp + k * TM);
                ulonglong2 w0 = *(const ulonglong2*)(wp + k * HDIM);
                ulonglong2 w1p = *(const ulonglong2*)(wp + k * HDIM + 4);
                unsigned long long bv2[4] = {w0.x, w0.y, w1p.x, w1p.y};
                float av[4] = {a0.x, a0.y, a0.z, a0.w};
                #pragma unroll
                for (int i = 0; i < 4; i++) {
                    unsigned long long a2 = pack2same(av[i]);
                    #pragma unroll
                    for (int jp = 0; jp < 4; jp++)
                        acc2[i][jp] = fma2(a2, bv2[jp], acc2[i][jp]);
                }
            }
            __syncthreads();   // HsT reads done -> overwrite with H3

            #pragma unroll
            for (int i = 0; i < 4; i++) {
                int m = ty * 4 + i;
                #pragma unroll
                for (int jp = 0; jp < 4; jp++) {
                    float lo, hi;
                    unpack2(acc2[i][jp], lo, hi);
                    int n = tx * 8 + jp * 2;
                    H3[m * 129 + n]     = softplus_x(__fadd_rn(lo, b2s[n]));
                    H3[m * 129 + n + 1] = softplus_x(__fadd_rn(hi, b2s[n + 1]));
                }
            }
            __syncthreads();

            // layer 3: gemv2T-8 order + fused epilogues
            {
                int grp = tid >> 3;
                int l8  = tid & 7;
                #pragma unroll
                for (int rep = 0; rep < 2; rep++) {
                    int m = rep * 32 + grp;
                    const float* hrow = H3 + m * 129;
                    float p = 0.0f;
                    #pragma unroll
                    for (int i = 0; i < 16; i++)
                        p = __fmaf_rn(hrow[l8 + 8 * i], w3s[l8 + 8 * i], p);
                    p = __fadd_rn(p, __shfl_down_sync(0xffffffffu, p, 4, 8));
                    p = __fadd_rn(p, __shfl_down_sync(0xffffffffu, p, 2, 8));
                    p = __fadd_rn(p, __shfl_down_sync(0xffffffffu, p, 1, 8));
                    if (l8 == 0) {
                        float corr = __fadd_rn(p, b3s[0]);
                        float px = Ps[m * 4 + 0], py = Ps[m * 4 + 1], pz = Ps[m * 4 + 2];
                        float s2 = __fadd_rn(__fadd_rn(__fmul_rn(px, px), __fmul_rn(py, py)), __fmul_rn(pz, pz));
                        float nr = __fsqrt_rn(s2);
                        float sv = __fadd_rn(__fsub_rn(nr, 1.0f), __fmul_rn(0.1f, corr));
                        int oi = oix[m];
                        if (MODE == 1) {
                            svs[m] = sv;
                        } else if (oi >= 0) {
                            int ray = oi;
                            if (FUSE == 0) {
                                outp[ray] = sv;
                            } else if (FUSE == 1) {
                                outp[ray] = sv;
                                if (sv < 0.f) {
                                    if (side == 0) {
                                        g_start[ray] = __fsub_rn(g_start[ray], __fmul_rn(0.5f, g_curr_s[ray]));
                                        int pp = atomicAdd(&g_cnt[xA], 1); g_lc[pp] = ray;
                                    } else {
                                        g_end[ray] = __fadd_rn(g_end[ray], __fmul_rn(0.5f, g_curr_e[ray]));
                                        int pp = atomicAdd(&g_cnt[xB], 1); g_ld[pp] = ray;
                                    }
                                }
                            } else {
                                float smv = sv;
                                float zl = g_zlow[ray], zh = g_zhigh[ray], sl = g_slow[ray], sh = g_shigh[ray];
                                float zp = g_zpred[ray];
                                if (smv > 0.f) { zl = zp; sl = smv; }
                                if (smv < 0.f) { zh = zp; sh = smv; }
                                float num = __fmul_rn(-sl, __fsub_rn(zh, zl));
                                float den = __fadd_rn(__fsub_rn(sh, sl), 1e-10f);
                                zp = __fadd_rn(__fdiv_rn(num, den), zl);
                                g_zlow[ray] = zl; g_zhigh[ray] = zh; g_slow[ray] = sl; g_shigh[ray] = sh;
                                g_zpred[ray] = zp;
                            }
                        }
                    }
                }
            }

            // MODE 1: tile = 1 ray; fused argmin reduce + secant init
            if (MODE == 1) {
                __syncthreads();
                int warp = tid >> 5, lane = tid & 31;
                if (warp == 0 && lb < rcnt) {
                    int ray = list[lb];
                    const float* sp = svs;
                    float s0 = sp[lane];
                    float s1 = sp[lane + 32];
                    float sg0 = (s0 > 0.f ? 1.f : (s0 < 0.f ? -1.f : 0.f));
                    float sg1 = (s1 > 0.f ? 1.f : (s1 < 0.f ? -1.f : 0.f));
                    float t0 = sg0 * (float)(64 - lane);
                    float t1 = sg1 * (float)(32 - lane);

                    float bv; int bi;
                    if (t1 < t0) { bv = t1; bi = lane + 32; } else { bv = t0; bi = lane; }
                    float cv; int ci;
                    if (s1 < s0) { cv = s1; ci = lane + 32; } else { cv = s0; ci = lane; }
                    #pragma unroll
                    for (int off = 16; off > 0; off >>= 1) {
                        float ov = __shfl_down_sync(0xffffffffu, bv, off);
                        int   oi2 = __shfl_down_sync(0xffffffffu, bi, off);
                        if (ov < bv || (ov == bv && oi2 < bi)) { bv = ov; bi = oi2; }
                        float pv = __shfl_down_sync(0xffffffffu, cv, off);
                        int   pi = __shfl_down_sync(0xffffffffu, ci, off);
                        if (pv < cv || (pv == cv && pi < ci)) { cv = pv; ci = pi; }
                    }
                    if (lane == 0) {
                        int idx = bi;
                        bool net = (bv < 0.f);
                        int out_idx = ci;
                        bool ob = (obj[ray] != 0);
                        bool p_out = !(ob && net);
                        int sel = p_out ? out_idx : idx;
                        float s = g_start[ray], e = g_end[ray];
                        g_cand[ray]  = ptsint(s, e, lint(sel));
                        g_convf[ray] = net ? 1 : 0;
                        if (net && ob) {
                            g_secf[ray] = 1;
                            int il = (idx + 63) & 63;
                            float zh = ptsint(s, e, lint(idx));
                            float zl = ptsint(s, e, lint(il));
                            float sh = sp[idx];
                            float sl = sp[il];
                            g_zlow[ray] = zl; g_zhigh[ray] = zh; g_slow[ray] = sl; g_shigh[ray] = sh;
                            float num = __fmul_rn(-sl, __fsub_rn(zh, zl));
                            float den = __fadd_rn(__fsub_rn(sh, sl), 1e-10f);
                            g_zpred[ray] = __fadd_rn(__fdiv_rn(num, den), zl);
                            int pp = atomicAdd(&g_cnt[xA], 1); g_ls[pp] = ray;
                        }
                    }
                }
            }
            __syncthreads();   // epilogue writes visible before next iter / tile
        }
    }
}

// ---------------- persistent kernel: whole pipeline ----------------
__global__ void __launch_bounds__(256, 4) persist_kernel(
    int N, int nb,
    const float* __restrict__ rayo, const float* __restrict__ rayd,
    const float* __restrict__ fb,
    const float* __restrict__ W1, const float* __restrict__ b1,
    const float* __restrict__ W2, const float* __restrict__ b2,
    const float* __restrict__ W3, const float* __restrict__ b3,
    const int* __restrict__ obj, const int* __restrict__ mi,
    float* __restrict__ out)
{
    extern __shared__ float sbuf[];
    float* w1s = sbuf + SOFF_W1;
    float* b1s = sbuf + SOFF_B1;
    float* b2s = sbuf + SOFF_B2;
    float* w3s = sbuf + SOFF_W3;
    float* b3s = sbuf + SOFF_B3;

    const int tid = threadIdx.x;
    const int gt = blockIdx.x * 256 + tid;
    const int gs = nb * 256;

    // weights -> smem once for the whole run
    for (int i = tid; i < 3 * HDIM; i += 256) w1s[i] = W1[i];
    if (tid < HDIM) { b1s[tid] = b1[tid]; b2s[tid] = b2[tid]; w3s[tid] = W3[tid]; }
    if (tid == 0) b3s[0] = b3[0];
    __syncthreads();

    // ---- init phase ----
    for (int i = gt; i < N; i += gs) {
        g_start[i] = fb[2 * i];
        g_end[i]   = fb[2 * i + 1];
        unsigned char m = mi[i] ? 1 : 0;
        g_uf_s[i] = m; g_uf_e[i] = m;
        g_next_s[i] = 0.f; g_next_e[i] = 0.f;
        g_workf[i] = 0; g_secf[i] = 0; g_convf[i] = 0;
        if (m) { int p = atomicAdd(&g_cnt[0], 1); g_la[p] = i; }
    }
    gridbar(nb);

    // ---- initial next_s/next_e ----
    eval_phase<0, 0, 2, 1>(0, 0, 0, 0, nb, rayo, rayd, W2, g_la, g_la,
                           g_start, g_end, g_next_s, g_next_e, obj);
    gridbar(nb);

    // ---- sphere tracing loop ----
    for (int it = 0; it < 10; it++) {
        int c1 = 1 + it * 4, c2 = 2 + it * 4, c3 = 3 + it * 4, c4 = 4 + it * 4;
        int apply_lt = (it > 0) ? 1 : 0;
        for (int i = gt; i < N; i += gs) {
            unsigned char us = g_uf_s[i], ue = g_uf_e[i];
            float s = g_start[i], e = g_end[i];
            if (apply_lt) { unsigned char lt = (s < e) ? 1 : 0; us &= lt; ue &= lt; }
            float cs = us ? g_next_s[i] : 0.f; if (cs <= THRS) cs = 0.f;
            float ce = ue ? g_next_e[i] : 0.f; if (ce <= THRS) ce = 0.f;
            us = (us && cs > THRS) ? 1 : 0;
            ue = (ue && ce > THRS) ? 1 : 0;
            if (us) s = __fadd_rn(s, cs);
            if (ue) e = __fsub_rn(e, ce);
            g_start[i] = s; g_end[i] = e;
            g_curr_s[i] = cs; g_curr_e[i] = ce;
            g_uf_s[i] = us; g_uf_e[i] = ue;
            if (!us) g_next_s[i] = 0.f;
            if (!ue) g_next_e[i] = 0.f;
            if (us) { int p = atomicAdd(&g_cnt[c1], 1); g_la[p] = i; }
            if (ue) { int p = atomicAdd(&g_cnt[c2], 1); g_lb[p] = i; }
        }
        gridbar(nb);
        eval_phase<0, 1, 2, 1>(c1, c2, c3, c4, nb, rayo, rayd, W2, g_la, g_lb,
                               g_start, g_end, g_next_s, g_next_e, obj);
        gridbar(nb);
        eval_phase<0, 0, 2, 1>(c3, c4, 0, 0, nb, rayo, rayd, W2, g_lc, g_ld,
                               g_start, g_end, g_next_s, g_next_e, obj);
        gridbar(nb);
    }

    // ---- work mask ----
    for (int i = gt; i < N; i += gs) {
        unsigned char us = g_uf_s[i];
        if (!(g_start[i] < g_end[i])) us = 0;
        unsigned char w = (us && (g_next_s[i] > THRS)) ? 1 : 0;
        g_workf[i] = w;
        if (w) { int p = atomicAdd(&g_cnt[48], 1); g_lw[p] = i; }
    }
    gridbar(nb);

    // ---- dense 64-step march + fused reduce + secant init ----
    eval_phase<1, 0, 1, 1>(48, 48, 49, 49, nb, rayo, rayd, W2, g_lw, g_lw,
                           g_start, g_start, g_next_s, g_next_s, obj);
    gridbar(nb);

    // ---- secant: 8 in-tile iterations, no grid barriers (per-ray independent)
    eval_phase<0, 2, 1, 8>(49, 49, 0, 0, nb, rayo, rayd, W2, g_ls, g_ls,
                           g_zpred, g_zpred, g_next_s, g_next_s, obj);
    gridbar(nb);

    // ---- assembly ----
    for (int i = gt; i < N; i += gs) {
        float px = 0.f, py = 0.f, pz = 0.f, dist = 0.f;
        if (g_secf[i]) {
            float t = g_zpred[i];
            px = __fadd_rn(rayo[i*3+0], __fmul_rn(t, rayd[i*3+0]));
            py = __fadd_rn(rayo[i*3+1], __fmul_rn(t, rayd[i*3+1]));
            pz = __fadd_rn(rayo[i*3+2], __fmul_rn(t, rayd[i*3+2]));
            dist = t;
        } else if (g_workf[i]) {
            float t = g_cand[i];
            px = __fadd_rn(rayo[i*3+0], __fmul_rn(t, rayd[i*3+0]));
            py = __fadd_rn(rayo[i*3+1], __fmul_rn(t, rayd[i*3+1]));
            pz = __fadd_rn(rayo[i*3+2], __fmul_rn(t, rayd[i*3+2]));
            dist = t;
        }
        out[i*5+0] = px; out[i*5+1] = py; out[i*5+2] = pz;
        out[i*5+3] = dist;
        out[i*5+4] = g_convf[i] ? 1.0f : 0.0f;
    }
}

// ---------------- counter reset ----------------
__global__ void reset_kernel() {
    if (threadIdx.x < 64) g_cnt[threadIdx.x] = 0;
}

// ---------------- host orchestration ----------------
extern "C" void kernel_launch(void* const* d_in, const int* in_sizes, int n_in,
                              void* d_out, int out_size)
{
    const float* rayo = (const float*)d_in[0];
    const float* rayd = (const float*)d_in[1];
    const float* fb   = (const float*)d_in[2];
    const float* W1   = (const float*)d_in[3];
    const float* b1   = (const float*)d_in[4];
    const float* W2   = (const float*)d_in[5];
    const float* b2   = (const float*)d_in[6];
    const float* W3   = (const float*)d_in[7];
    const float* b3   = (const float*)d_in[8];
    const int* obj    = (const int*)d_in[9];
    const int* mi     = (const int*)d_in[10];
    int N = in_sizes[0] / 3;
    float* out = (float*)d_out;

    cudaFuncSetAttribute(persist_kernel, cudaFuncAttributeMaxDynamicSharedMemorySize, EVAL_SMEM);

    int dev = 0, sms = 0, occ = 0;
    cudaGetDevice(&dev);
    cudaDeviceGetAttribute(&sms, cudaDevAttrMultiProcessorCount, dev);
    cudaOccupancyMaxActiveBlocksPerMultiprocessor(&occ, persist_kernel, 256, EVAL_SMEM);
    if (occ < 1) occ = 1;
    int nb = sms * occ;
    if (nb < 1) nb = 148;

    reset_kernel<<<1, 64>>>();
    persist_kernel<<<nb, 256, EVAL_SMEM>>>(N, nb, rayo, rayd, fb,
                                           W1, b1, W2, b2, W3, b3, obj, mi, out);
    (void)n_in; (void)out_size; (void)b2;
}